// round 6
// baseline (speedup 1.0000x reference)
#include <cuda_runtime.h>
#include <cuda_bf16.h>
#include <cuda_fp16.h>
#include <cstdint>
#include <math.h>

// Problem constants
#define L_SEQ 2048
#define B_BATCH 64
#define ENC 512
#define ATTN 64
#define HIDDEN 512
#define M_TOTAL (L_SEQ * B_BATCH)   // 131072
#define NSPLIT 16
#define NKSTEP 32                   // 512 / 16

// ---------------- device-global scratch (no allocs allowed) ----------------
__device__ float g_hidb[B_BATCH * ATTN];               // hid @ W_hidden + b_attn, (b, a)
__device__ float g_scoresT[B_BATCH * L_SEQ];           // scores transposed (b, l)
__device__ float g_stats[B_BATCH * 2];                 // per-b: max, 1/sumexp
__device__ float g_partial[NSPLIT * B_BATCH * ENC];    // partial weighted sums
// B fragments, mma-native with PERMUTED k (phys 2t,2t+1 <- logical 4t,4t+1;
// phys 2t+8,2t+9 <- logical 4t+2,4t+3): [kstep][ntile][lane] -> uint4(b0hi,b1hi,b0lo,b1lo)
__device__ uint4 g_Bfrag[NKSTEP * 8 * 32];

// ---------------- helpers ----------------
__device__ __forceinline__ unsigned pack_h2(float x, float y) {
    const __half2 h = __float22half2_rn(make_float2(x, y));
    return *(const unsigned*)&h;
}
__device__ __forceinline__ unsigned pack_hilo(float x, float y, unsigned& lo_out) {
    const __half hx = __float2half_rn(x);
    const __half hy = __float2half_rn(y);
    const __half lx = __float2half_rn(x - __half2float(hx));
    const __half ly = __float2half_rn(y - __half2float(hy));
    lo_out = ((unsigned)__half_as_ushort(ly) << 16) | __half_as_ushort(lx);
    return ((unsigned)__half_as_ushort(hy) << 16) | __half_as_ushort(hx);
}

__device__ __forceinline__ void mma_f16(float* d, const unsigned* a, unsigned b0, unsigned b1) {
    asm volatile(
        "mma.sync.aligned.m16n8k16.row.col.f32.f16.f16.f32 "
        "{%0,%1,%2,%3}, {%4,%5,%6,%7}, {%8,%9}, {%0,%1,%2,%3};"
        : "+f"(d[0]), "+f"(d[1]), "+f"(d[2]), "+f"(d[3])
        : "r"(a[0]), "r"(a[1]), "r"(a[2]), "r"(a[3]), "r"(b0), "r"(b1));
}

// ---------------- Kernel 0: precompute B fragments (permuted-k fp16 hi/lo) ----------
__global__ void __launch_bounds__(256) prep_w_kernel(const float* __restrict__ W) {
    const int idx = blockIdx.x * 256 + threadIdx.x;   // 0 .. 8191
    if (idx >= NKSTEP * 8 * 32) return;
    const int lane = idx & 31;
    const int nt = (idx >> 5) & 7;
    const int s = idx >> 8;
    const int t = lane & 3;
    const int g = lane >> 2;
    const int n = nt * 8 + g;
    const int k0 = s * 16 + t * 4;   // this lane's contiguous logical-k quad
    uint4 r;
    unsigned lo;
    // physical k 2t,2t+1   <- logical k0, k0+1
    r.x = pack_hilo(W[(size_t)k0 * ATTN + n],       W[(size_t)(k0 + 1) * ATTN + n], lo);
    r.z = lo;
    // physical k 2t+8,2t+9 <- logical k0+2, k0+3
    r.y = pack_hilo(W[(size_t)(k0 + 2) * ATTN + n], W[(size_t)(k0 + 3) * ATTN + n], lo);
    r.w = lo;
    g_Bfrag[idx] = r;
}

// ---------------- Kernel 1: hid = hidden @ W_hidden + b_attn ----------------
__global__ void __launch_bounds__(64) hid_kernel(const float* __restrict__ hidden,
                                                 const float* __restrict__ Wh,
                                                 const float* __restrict__ b_attn) {
    __shared__ float sh[HIDDEN];
    int b = blockIdx.x;
    int tid = threadIdx.x;
    for (int k = tid; k < HIDDEN; k += 64) sh[k] = hidden[b * HIDDEN + k];
    __syncthreads();
    float acc = b_attn[tid];
#pragma unroll 8
    for (int k = 0; k < HIDDEN; k++)
        acc = fmaf(sh[k], Wh[k * ATTN + tid], acc);
    g_hidb[b * ATTN + tid] = acc;
}

// ---------------- Kernel 1b: zero the partial buffer (also shifts score to launch #4
//                  so ncu's fixed capture slot profiles the GEMM) --------------------
__global__ void __launch_bounds__(256) zero_partial_kernel() {
    const int idx = blockIdx.x * 256 + threadIdx.x;
    *(float4*)(g_partial + (size_t)idx * 4) = make_float4(0.f, 0.f, 0.f, 0.f);
}

// ---------------- Kernel 2: fp16 2-product HMMA GEMM + tanh*v epilogue ----------------
// Warp owns 32 rows (2 m16 tiles). A fragments via ONE ld.128 per row per k-step
// (permuted-k layout), with 1-deep explicit prefetch to hide DRAM latency.
__global__ void __launch_bounds__(256, 2) score_kernel(const float* __restrict__ A,
                                                       const float* __restrict__ v) {
    const int tid = threadIdx.x;
    const int w = tid >> 5;
    const int lane = tid & 31;
    const int t = lane & 3;
    const int g = lane >> 2;
    const int m0w = blockIdx.x * 256 + w * 32;
    const int r0 = m0w + g;          // mtile0 rows: r0, r0+8
    const int r2 = m0w + g + 16;     // mtile1 rows: r2, r2+8
    // per-kstep stride = 16 floats = 4 float4; lane's quad = index t
    const float4* __restrict__ q0 = (const float4*)(A + (size_t)r0 * ENC) + t;
    const float4* __restrict__ q1 = (const float4*)(A + (size_t)(r0 + 8) * ENC) + t;
    const float4* __restrict__ q2 = (const float4*)(A + (size_t)r2 * ENC) + t;
    const float4* __restrict__ q3 = (const float4*)(A + (size_t)(r2 + 8) * ENC) + t;

    float d0[8][4], d1[8][4];
#pragma unroll
    for (int nt = 0; nt < 8; nt++)
#pragma unroll
        for (int j = 0; j < 4; j++) { d0[nt][j] = 0.0f; d1[nt][j] = 0.0f; }

    float4 f0 = q0[0], f1 = q1[0], f2 = q2[0], f3 = q3[0];

#pragma unroll 1
    for (int s = 0; s < NKSTEP; s++) {
        // prefetch next k-step's A while this step's MMAs run
        float4 n0, n1, n2, n3;
        if (s < NKSTEP - 1) {
            n0 = q0[(s + 1) * 4]; n1 = q1[(s + 1) * 4];
            n2 = q2[(s + 1) * 4]; n3 = q3[(s + 1) * 4];
        }
        unsigned a0[4], a1[4];
        a0[0] = pack_h2(f0.x, f0.y);   // row r0,   phys k 2t,2t+1
        a0[1] = pack_h2(f1.x, f1.y);   // row r0+8
        a0[2] = pack_h2(f0.z, f0.w);   // row r0,   phys k 2t+8,2t+9
        a0[3] = pack_h2(f1.z, f1.w);
        a1[0] = pack_h2(f2.x, f2.y);
        a1[1] = pack_h2(f3.x, f3.y);
        a1[2] = pack_h2(f2.z, f2.w);
        a1[3] = pack_h2(f3.z, f3.w);

        const uint4* __restrict__ bp = g_Bfrag + (s << 8) + lane;
#pragma unroll
        for (int nt = 0; nt < 8; nt++) {
            const uint4 bf = bp[nt << 5];
            mma_f16(d0[nt], a0, bf.x, bf.y);   // Ahi * Bhi
            mma_f16(d0[nt], a0, bf.z, bf.w);   // Ahi * Blo
            mma_f16(d1[nt], a1, bf.x, bf.y);
            mma_f16(d1[nt], a1, bf.z, bf.w);
        }
        f0 = n0; f1 = n1; f2 = n2; f3 = n3;
    }

    // Epilogue: scores = sum_n tanh(d + hid[b][n]) * v[n]; 4 rows per lane-group
    const int rows[4] = { r0, r0 + 8, r2, r2 + 8 };
    float p[4] = { 0.f, 0.f, 0.f, 0.f };
#pragma unroll
    for (int nt = 0; nt < 8; nt++) {
        const int n0i = nt * 8 + t * 2;
        const float v0 = v[n0i], v1 = v[n0i + 1];
#pragma unroll
        for (int rr = 0; rr < 4; rr++) {
            const float* hb = g_hidb + (rows[rr] & 63) * ATTN;
            const float e0 = (rr < 2) ? d0[nt][(rr & 1) * 2]     : d1[nt][(rr & 1) * 2];
            const float e1 = (rr < 2) ? d0[nt][(rr & 1) * 2 + 1] : d1[nt][(rr & 1) * 2 + 1];
            p[rr] += tanhf(e0 + hb[n0i]) * v0 + tanhf(e1 + hb[n0i + 1]) * v1;
        }
    }
#pragma unroll
    for (int rr = 0; rr < 4; rr++) {
        p[rr] += __shfl_xor_sync(0xFFFFFFFFu, p[rr], 1);
        p[rr] += __shfl_xor_sync(0xFFFFFFFFu, p[rr], 2);
    }
    if (t == 0) {
#pragma unroll
        for (int rr = 0; rr < 4; rr++)
            g_scoresT[(rows[rr] & 63) * L_SEQ + (rows[rr] >> 6)] = p[rr];
    }
}

// ---------------- Kernel 3a: per-b masked softmax stats (smem-staged) ----------------
__global__ void __launch_bounds__(256) stats_kernel(const int* __restrict__ lens) {
    __shared__ float red[32];
    const int b = blockIdx.x;
    const int tid = threadIdx.x;
    const int lane = tid & 31;
    const int wrp = tid >> 5;
    const int len = lens[b];
    const float* s = g_scoresT + b * L_SEQ;

    float vals[8];
#pragma unroll
    for (int i = 0; i < 2; i++) {
        const float4 f = *(const float4*)(s + (i * 256 + tid) * 4);
        vals[i * 4 + 0] = f.x; vals[i * 4 + 1] = f.y;
        vals[i * 4 + 2] = f.z; vals[i * 4 + 3] = f.w;
    }
    float mx = -INFINITY;
#pragma unroll
    for (int i = 0; i < 2; i++)
#pragma unroll
        for (int j = 0; j < 4; j++) {
            const int l = (i * 256 + tid) * 4 + j;
            if (l < len) mx = fmaxf(mx, vals[i * 4 + j]);
        }
#pragma unroll
    for (int o = 16; o > 0; o >>= 1) mx = fmaxf(mx, __shfl_xor_sync(0xFFFFFFFFu, mx, o));
    if (lane == 0) red[wrp] = mx;
    __syncthreads();
    if (wrp == 0) {
        float m = (lane < 8) ? red[lane] : -INFINITY;
#pragma unroll
        for (int o = 4; o > 0; o >>= 1) m = fmaxf(m, __shfl_xor_sync(0xFFFFFFFFu, m, o));
        if (lane == 0) red[16] = m;
    }
    __syncthreads();
    mx = red[16];

    float sum = 0.0f;
#pragma unroll
    for (int i = 0; i < 2; i++)
#pragma unroll
        for (int j = 0; j < 4; j++) {
            const int l = (i * 256 + tid) * 4 + j;
            if (l < len) sum += expf(vals[i * 4 + j] - mx);
        }
#pragma unroll
    for (int o = 16; o > 0; o >>= 1) sum += __shfl_xor_sync(0xFFFFFFFFu, sum, o);
    if (lane == 0) red[wrp] = sum;
    __syncthreads();
    if (tid == 0) {
        float tot = 0.0f;
#pragma unroll
        for (int i = 0; i < 8; i++) tot += red[i];
        g_stats[b * 2 + 0] = mx;
        g_stats[b * 2 + 1] = 1.0f / tot;
    }
}

// ---------------- Kernel 3b: weighted partial sums (float4, 2-way row split) ----------------
__global__ void __launch_bounds__(256) weighted_kernel(const float* __restrict__ enc,
                                                       const int* __restrict__ lens) {
    __shared__ float wsh[128];
    __shared__ float red[512];
    const int s = blockIdx.x;
    const int b = blockIdx.y;
    const int tid = threadIdx.x;
    const int l0 = s * (L_SEQ / NSPLIT);
    const int len = lens[b];
    float* pbase = g_partial + ((size_t)(s * B_BATCH + b)) * ENC;

    if (l0 >= len) return;   // partials pre-zeroed by zero_partial_kernel

    if (tid < 128) {
        const int l = l0 + tid;
        float w = 0.0f;
        if (l < len)
            w = expf(g_scoresT[b * L_SEQ + l] - g_stats[2 * b]) * g_stats[2 * b + 1];
        wsh[tid] = w;
    }
    __syncthreads();

    const int lim = min(128, len - l0);
    const int d4 = tid & 127;
    const int half = tid >> 7;
    float4 acc = make_float4(0.f, 0.f, 0.f, 0.f);
#pragma unroll 4
    for (int i = half; i < lim; i += 2) {
        const float w = wsh[i];
        const float4 e = *(const float4*)(enc + ((size_t)(l0 + i) * B_BATCH + b) * ENC + d4 * 4);
        acc.x = fmaf(w, e.x, acc.x);
        acc.y = fmaf(w, e.y, acc.y);
        acc.z = fmaf(w, e.z, acc.z);
        acc.w = fmaf(w, e.w, acc.w);
    }
    if (half == 1) *(float4*)&red[d4 * 4] = acc;
    __syncthreads();
    if (half == 0) {
        const float4 o = *(const float4*)&red[d4 * 4];
        acc.x += o.x; acc.y += o.y; acc.z += o.z; acc.w += o.w;
        *(float4*)(pbase + d4 * 4) = acc;
    }
}

// ---------------- Kernel 3c: reduce partials ----------------
__global__ void __launch_bounds__(256) reduce_kernel(float* __restrict__ out) {
    const int idx = blockIdx.x * 256 + threadIdx.x;
    float4 sum = make_float4(0.f, 0.f, 0.f, 0.f);
#pragma unroll
    for (int s = 0; s < NSPLIT; s++) {
        const float4 p = *(const float4*)(g_partial + (size_t)s * (B_BATCH * ENC) + idx * 4);
        sum.x += p.x; sum.y += p.y; sum.z += p.z; sum.w += p.w;
    }
    *(float4*)(out + idx * 4) = sum;
}

// ---------------- Launch ----------------
extern "C" void kernel_launch(void* const* d_in, const int* in_sizes, int n_in,
                              void* d_out, int out_size) {
    const float* enc    = (const float*)d_in[0];  // (L, B, 512)
    const int*   lens   = (const int*)d_in[1];    // (B,)
    const float* hidden = (const float*)d_in[2];  // (B, 512)
    const float* W_enc  = (const float*)d_in[3];  // (512, 64)
    const float* b_attn = (const float*)d_in[4];  // (64,)
    const float* W_hid  = (const float*)d_in[5];  // (512, 64)
    const float* v      = (const float*)d_in[6];  // (64,)
    float* out = (float*)d_out;                   // (B, 512)

    prep_w_kernel<<<32, 256>>>(W_enc);                           // 1
    hid_kernel<<<B_BATCH, 64>>>(hidden, W_hid, b_attn);          // 2
    zero_partial_kernel<<<NSPLIT * B_BATCH * ENC / 1024, 256>>>();// 3
    score_kernel<<<M_TOTAL / 256, 256>>>(enc, v);                // 4  <- ncu capture slot
    stats_kernel<<<B_BATCH, 256>>>(lens);                        // 5
    weighted_kernel<<<dim3(NSPLIT, B_BATCH), 256>>>(enc, lens);  // 6
    reduce_kernel<<<(B_BATCH * ENC) / (256 * 4), 256>>>(out);    // 7
}

// round 7
// speedup vs baseline: 1.1044x; 1.1044x over previous
#include <cuda_runtime.h>
#include <cuda_bf16.h>
#include <cuda_fp16.h>
#include <cstdint>
#include <math.h>

// Problem constants
#define L_SEQ 2048
#define B_BATCH 64
#define ENC 512
#define ATTN 64
#define HIDDEN 512
#define M_TOTAL (L_SEQ * B_BATCH)   // 131072
#define NSPLIT 16
#define NKSTEP 32                   // 512 / 16
#define STAGES 4                    // cp.async pipeline depth
#define STAGE_FLOATS 4096           // 256 rows * 16 floats
#define SMEM_BYTES (STAGES * STAGE_FLOATS * 4)   // 64 KB

// ---------------- device-global scratch (no allocs allowed) ----------------
__device__ float g_hidb[B_BATCH * ATTN];               // hid @ W_hidden + b_attn, (b, a)
__device__ float g_scoresT[B_BATCH * L_SEQ];           // scores transposed (b, l)
__device__ float g_stats[B_BATCH * 2];                 // per-b: max, 1/sumexp
__device__ float g_partial[NSPLIT * B_BATCH * ENC];    // partial weighted sums
// B fragments, mma-native with PERMUTED k (phys 2t,2t+1 <- logical 4t,4t+1;
// phys 2t+8,2t+9 <- logical 4t+2,4t+3): [kstep][ntile][lane] -> uint4(b0hi,b1hi,b0lo,b1lo)
__device__ uint4 g_Bfrag[NKSTEP * 8 * 32];

// ---------------- helpers ----------------
__device__ __forceinline__ unsigned pack_h2(float x, float y) {
    const __half2 h = __float22half2_rn(make_float2(x, y));
    return *(const unsigned*)&h;
}
__device__ __forceinline__ unsigned pack_hilo(float x, float y, unsigned& lo_out) {
    const __half hx = __float2half_rn(x);
    const __half hy = __float2half_rn(y);
    const __half lx = __float2half_rn(x - __half2float(hx));
    const __half ly = __float2half_rn(y - __half2float(hy));
    lo_out = ((unsigned)__half_as_ushort(ly) << 16) | __half_as_ushort(lx);
    return ((unsigned)__half_as_ushort(hy) << 16) | __half_as_ushort(hx);
}
__device__ __forceinline__ void mma_f16(float* d, const unsigned* a, unsigned b0, unsigned b1) {
    asm volatile(
        "mma.sync.aligned.m16n8k16.row.col.f32.f16.f16.f32 "
        "{%0,%1,%2,%3}, {%4,%5,%6,%7}, {%8,%9}, {%0,%1,%2,%3};"
        : "+f"(d[0]), "+f"(d[1]), "+f"(d[2]), "+f"(d[3])
        : "r"(a[0]), "r"(a[1]), "r"(a[2]), "r"(a[3]), "r"(b0), "r"(b1));
}
__device__ __forceinline__ uint32_t smem_u32(const void* p) {
    uint32_t a;
    asm("{ .reg .u64 t; cvta.to.shared.u64 t, %1; cvt.u32.u64 %0, t; }" : "=r"(a) : "l"(p));
    return a;
}
__device__ __forceinline__ void cp16(uint32_t dst_smem, const void* src_g) {
    asm volatile("cp.async.cg.shared.global [%0], [%1], 16;" :: "r"(dst_smem), "l"(src_g));
}
#define CP_COMMIT() asm volatile("cp.async.commit_group;" ::: "memory")
#define CP_WAIT(n)  asm volatile("cp.async.wait_group %0;" :: "n"(n) : "memory")

// ---------------- Kernel 0: precompute B fragments (permuted-k fp16 hi/lo) ----------
__global__ void __launch_bounds__(256) prep_w_kernel(const float* __restrict__ W) {
    const int idx = blockIdx.x * 256 + threadIdx.x;   // 0 .. 8191
    if (idx >= NKSTEP * 8 * 32) return;
    const int lane = idx & 31;
    const int nt = (idx >> 5) & 7;
    const int s = idx >> 8;
    const int t = lane & 3;
    const int g = lane >> 2;
    const int n = nt * 8 + g;
    const int k0 = s * 16 + t * 4;   // this lane's contiguous logical-k quad
    uint4 r;
    unsigned lo;
    r.x = pack_hilo(W[(size_t)k0 * ATTN + n],       W[(size_t)(k0 + 1) * ATTN + n], lo);
    r.z = lo;
    r.y = pack_hilo(W[(size_t)(k0 + 2) * ATTN + n], W[(size_t)(k0 + 3) * ATTN + n], lo);
    r.w = lo;
    g_Bfrag[idx] = r;
}

// ---------------- Kernel 1: hid = hidden @ W_hidden + b_attn ----------------
__global__ void __launch_bounds__(64) hid_kernel(const float* __restrict__ hidden,
                                                 const float* __restrict__ Wh,
                                                 const float* __restrict__ b_attn) {
    __shared__ float sh[HIDDEN];
    int b = blockIdx.x;
    int tid = threadIdx.x;
    for (int k = tid; k < HIDDEN; k += 64) sh[k] = hidden[b * HIDDEN + k];
    __syncthreads();
    float acc = b_attn[tid];
#pragma unroll 8
    for (int k = 0; k < HIDDEN; k++)
        acc = fmaf(sh[k], Wh[k * ATTN + tid], acc);
    g_hidb[b * ATTN + tid] = acc;
}

// ---------------- Kernel 1b: zero partials (keeps score at ncu capture slot #4) ----
__global__ void __launch_bounds__(256) zero_partial_kernel() {
    const int idx = blockIdx.x * 256 + threadIdx.x;
    *(float4*)(g_partial + (size_t)idx * 4) = make_float4(0.f, 0.f, 0.f, 0.f);
}

// ---------------- Kernel 2: fp16 2-product HMMA GEMM, cp.async-pipelined A ---------
// CTA 256 threads = 8 warps; warp owns 32 rows (2 m16 tiles). A staged through a
// 4-deep cp.async smem pipeline (16KB/stage); B fragments via L1-resident LDG.
__global__ void __launch_bounds__(256, 2) score_kernel(const float* __restrict__ A,
                                                       const float* __restrict__ v) {
    extern __shared__ float sa[];   // STAGES * 4096 floats
    const uint32_t sb = smem_u32(sa);
    const int tid = threadIdx.x;
    const int w = tid >> 5;
    const int lane = tid & 31;
    const int t = lane & 3;
    const int g = lane >> 2;
    const int m0 = blockIdx.x * 256;
    const int lr0 = w * 32 + g;                 // local rows lr0, +8, +16, +24

    // cp.async mapping: thread copies 4 rows' 16B chunks per stage
    const int crow = tid >> 2;                  // 0..63 (+64*i)
    const int cq = tid & 3;                     // 16B chunk within 64B row slab
    const float* __restrict__ Ab = A + (size_t)m0 * ENC;

    float d0[8][4], d1[8][4];
#pragma unroll
    for (int nt = 0; nt < 8; nt++)
#pragma unroll
        for (int j = 0; j < 4; j++) { d0[nt][j] = 0.0f; d1[nt][j] = 0.0f; }

    // prologue: issue stages 0..STAGES-2
#pragma unroll
    for (int st = 0; st < STAGES - 1; st++) {
#pragma unroll
        for (int i = 0; i < 4; i++) {
            const int lr = crow + i * 64;
            cp16(sb + (st * STAGE_FLOATS + lr * 16 + cq * 4) * 4,
                 Ab + (size_t)lr * ENC + st * 16 + cq * 4);
        }
        CP_COMMIT();
    }

    const float* sr0 = sa + lr0 * 16 + t * 4;

#pragma unroll 1
    for (int s = 0; s < NKSTEP; s++) {
        CP_WAIT(STAGES - 2);        // stage s's copies (this thread's) complete
        __syncthreads();            // publish to CTA; also: slot (s-1)%S compute done

        // issue stage s+STAGES-1 into the slot freed last iteration
        const int sn = s + STAGES - 1;
        if (sn < NKSTEP) {
            const int slot = sn & (STAGES - 1);
#pragma unroll
            for (int i = 0; i < 4; i++) {
                const int lr = crow + i * 64;
                cp16(sb + (slot * STAGE_FLOATS + lr * 16 + cq * 4) * 4,
                     Ab + (size_t)lr * ENC + sn * 16 + cq * 4);
            }
        }
        CP_COMMIT();                // commit every iter (possibly empty) to keep counts aligned

        // compute stage s
        const float* sp = sr0 + (s & (STAGES - 1)) * STAGE_FLOATS;
        const float4 f0 = *(const float4*)(sp);
        const float4 f1 = *(const float4*)(sp + 8 * 16);
        const float4 f2 = *(const float4*)(sp + 16 * 16);
        const float4 f3 = *(const float4*)(sp + 24 * 16);
        unsigned a0[4], a1[4];
        a0[0] = pack_h2(f0.x, f0.y);
        a0[1] = pack_h2(f1.x, f1.y);
        a0[2] = pack_h2(f0.z, f0.w);
        a0[3] = pack_h2(f1.z, f1.w);
        a1[0] = pack_h2(f2.x, f2.y);
        a1[1] = pack_h2(f3.x, f3.y);
        a1[2] = pack_h2(f2.z, f2.w);
        a1[3] = pack_h2(f3.z, f3.w);

        const uint4* __restrict__ bp = g_Bfrag + (s << 8) + lane;
#pragma unroll
        for (int nt = 0; nt < 8; nt++) {
            const uint4 bf = bp[nt << 5];
            mma_f16(d0[nt], a0, bf.x, bf.y);   // Ahi * Bhi
            mma_f16(d0[nt], a0, bf.z, bf.w);   // Ahi * Blo
            mma_f16(d1[nt], a1, bf.x, bf.y);
            mma_f16(d1[nt], a1, bf.z, bf.w);
        }
    }

    // Epilogue: scores = sum_n tanh(d + hid[b][n]) * v[n]; 4 rows per lane-group
    const int r0 = m0 + lr0;
    const int rows[4] = { r0, r0 + 8, r0 + 16, r0 + 24 };
    float p[4] = { 0.f, 0.f, 0.f, 0.f };
#pragma unroll
    for (int nt = 0; nt < 8; nt++) {
        const int n0i = nt * 8 + t * 2;
        const float v0 = v[n0i], v1 = v[n0i + 1];
#pragma unroll
        for (int rr = 0; rr < 4; rr++) {
            const float* hb = g_hidb + (rows[rr] & 63) * ATTN;
            const float e0 = (rr < 2) ? d0[nt][(rr & 1) * 2]     : d1[nt][(rr & 1) * 2];
            const float e1 = (rr < 2) ? d0[nt][(rr & 1) * 2 + 1] : d1[nt][(rr & 1) * 2 + 1];
            p[rr] += tanhf(e0 + hb[n0i]) * v0 + tanhf(e1 + hb[n0i + 1]) * v1;
        }
    }
#pragma unroll
    for (int rr = 0; rr < 4; rr++) {
        p[rr] += __shfl_xor_sync(0xFFFFFFFFu, p[rr], 1);
        p[rr] += __shfl_xor_sync(0xFFFFFFFFu, p[rr], 2);
    }
    if (t == 0) {
#pragma unroll
        for (int rr = 0; rr < 4; rr++)
            g_scoresT[(rows[rr] & 63) * L_SEQ + (rows[rr] >> 6)] = p[rr];
    }
}

// ---------------- Kernel 3a: per-b masked softmax stats (smem-staged) ----------------
__global__ void __launch_bounds__(256) stats_kernel(const int* __restrict__ lens) {
    __shared__ float red[32];
    const int b = blockIdx.x;
    const int tid = threadIdx.x;
    const int lane = tid & 31;
    const int wrp = tid >> 5;
    const int len = lens[b];
    const float* s = g_scoresT + b * L_SEQ;

    float vals[8];
#pragma unroll
    for (int i = 0; i < 2; i++) {
        const float4 f = *(const float4*)(s + (i * 256 + tid) * 4);
        vals[i * 4 + 0] = f.x; vals[i * 4 + 1] = f.y;
        vals[i * 4 + 2] = f.z; vals[i * 4 + 3] = f.w;
    }
    float mx = -INFINITY;
#pragma unroll
    for (int i = 0; i < 2; i++)
#pragma unroll
        for (int j = 0; j < 4; j++) {
            const int l = (i * 256 + tid) * 4 + j;
            if (l < len) mx = fmaxf(mx, vals[i * 4 + j]);
        }
#pragma unroll
    for (int o = 16; o > 0; o >>= 1) mx = fmaxf(mx, __shfl_xor_sync(0xFFFFFFFFu, mx, o));
    if (lane == 0) red[wrp] = mx;
    __syncthreads();
    if (wrp == 0) {
        float m = (lane < 8) ? red[lane] : -INFINITY;
#pragma unroll
        for (int o = 4; o > 0; o >>= 1) m = fmaxf(m, __shfl_xor_sync(0xFFFFFFFFu, m, o));
        if (lane == 0) red[16] = m;
    }
    __syncthreads();
    mx = red[16];

    float sum = 0.0f;
#pragma unroll
    for (int i = 0; i < 2; i++)
#pragma unroll
        for (int j = 0; j < 4; j++) {
            const int l = (i * 256 + tid) * 4 + j;
            if (l < len) sum += expf(vals[i * 4 + j] - mx);
        }
#pragma unroll
    for (int o = 16; o > 0; o >>= 1) sum += __shfl_xor_sync(0xFFFFFFFFu, sum, o);
    if (lane == 0) red[wrp] = sum;
    __syncthreads();
    if (tid == 0) {
        float tot = 0.0f;
#pragma unroll
        for (int i = 0; i < 8; i++) tot += red[i];
        g_stats[b * 2 + 0] = mx;
        g_stats[b * 2 + 1] = 1.0f / tot;
    }
}

// ---------------- Kernel 3b: weighted partial sums (float4, 2-way row split) ----------------
__global__ void __launch_bounds__(256) weighted_kernel(const float* __restrict__ enc,
                                                       const int* __restrict__ lens) {
    __shared__ float wsh[128];
    __shared__ float red[512];
    const int s = blockIdx.x;
    const int b = blockIdx.y;
    const int tid = threadIdx.x;
    const int l0 = s * (L_SEQ / NSPLIT);
    const int len = lens[b];
    float* pbase = g_partial + ((size_t)(s * B_BATCH + b)) * ENC;

    if (l0 >= len) return;   // partials pre-zeroed by zero_partial_kernel

    if (tid < 128) {
        const int l = l0 + tid;
        float w = 0.0f;
        if (l < len)
            w = expf(g_scoresT[b * L_SEQ + l] - g_stats[2 * b]) * g_stats[2 * b + 1];
        wsh[tid] = w;
    }
    __syncthreads();

    const int lim = min(128, len - l0);
    const int d4 = tid & 127;
    const int half = tid >> 7;
    float4 acc = make_float4(0.f, 0.f, 0.f, 0.f);
#pragma unroll 4
    for (int i = half; i < lim; i += 2) {
        const float w = wsh[i];
        const float4 e = *(const float4*)(enc + ((size_t)(l0 + i) * B_BATCH + b) * ENC + d4 * 4);
        acc.x = fmaf(w, e.x, acc.x);
        acc.y = fmaf(w, e.y, acc.y);
        acc.z = fmaf(w, e.z, acc.z);
        acc.w = fmaf(w, e.w, acc.w);
    }
    if (half == 1) *(float4*)&red[d4 * 4] = acc;
    __syncthreads();
    if (half == 0) {
        const float4 o = *(const float4*)&red[d4 * 4];
        acc.x += o.x; acc.y += o.y; acc.z += o.z; acc.w += o.w;
        *(float4*)(pbase + d4 * 4) = acc;
    }
}

// ---------------- Kernel 3c: reduce partials ----------------
__global__ void __launch_bounds__(256) reduce_kernel(float* __restrict__ out) {
    const int idx = blockIdx.x * 256 + threadIdx.x;
    float4 sum = make_float4(0.f, 0.f, 0.f, 0.f);
#pragma unroll
    for (int s = 0; s < NSPLIT; s++) {
        const float4 p = *(const float4*)(g_partial + (size_t)s * (B_BATCH * ENC) + idx * 4);
        sum.x += p.x; sum.y += p.y; sum.z += p.z; sum.w += p.w;
    }
    *(float4*)(out + idx * 4) = sum;
}

// ---------------- Launch ----------------
extern "C" void kernel_launch(void* const* d_in, const int* in_sizes, int n_in,
                              void* d_out, int out_size) {
    const float* enc    = (const float*)d_in[0];  // (L, B, 512)
    const int*   lens   = (const int*)d_in[1];    // (B,)
    const float* hidden = (const float*)d_in[2];  // (B, 512)
    const float* W_enc  = (const float*)d_in[3];  // (512, 64)
    const float* b_attn = (const float*)d_in[4];  // (64,)
    const float* W_hid  = (const float*)d_in[5];  // (512, 64)
    const float* v      = (const float*)d_in[6];  // (64,)
    float* out = (float*)d_out;                   // (B, 512)

    cudaFuncSetAttribute(score_kernel, cudaFuncAttributeMaxDynamicSharedMemorySize, SMEM_BYTES);

    prep_w_kernel<<<32, 256>>>(W_enc);                            // 1
    hid_kernel<<<B_BATCH, 64>>>(hidden, W_hid, b_attn);           // 2
    zero_partial_kernel<<<NSPLIT * B_BATCH * ENC / 1024, 256>>>();// 3
    score_kernel<<<M_TOTAL / 256, 256, SMEM_BYTES>>>(enc, v);     // 4  <- ncu capture slot
    stats_kernel<<<B_BATCH, 256>>>(lens);                         // 5
    weighted_kernel<<<dim3(NSPLIT, B_BATCH), 256>>>(enc, lens);   // 6
    reduce_kernel<<<(B_BATCH * ENC) / (256 * 4), 256>>>(out);     // 7
}

// round 8
// speedup vs baseline: 1.3806x; 1.2501x over previous
#include <cuda_runtime.h>
#include <cuda_bf16.h>
#include <cuda_fp16.h>
#include <cstdint>
#include <math.h>

// Problem constants
#define L_SEQ 2048
#define B_BATCH 64
#define ENC 512
#define ATTN 64
#define HIDDEN 512
#define M_TOTAL (L_SEQ * B_BATCH)   // 131072
#define NSPLIT 16
#define NKSTEP 32                   // 512 / 16
#define STAGES 4                    // per-warp cp.async pipeline depth
#define WSTAGE 512                  // floats per warp-stage (32 rows x 16)
#define SMEM_BYTES (8 * STAGES * WSTAGE * 4)   // 64 KB

// ---------------- device-global scratch (no allocs allowed) ----------------
__device__ float g_hidb[B_BATCH * ATTN];               // hid @ W_hidden + b_attn, (b, a)
__device__ float g_scoresT[B_BATCH * L_SEQ];           // scores transposed (b, l)
__device__ float g_stats[B_BATCH * 2];                 // per-b: max, 1/sumexp
__device__ float g_partial[NSPLIT * B_BATCH * ENC];    // partial weighted sums
// B fragments, mma-native with PERMUTED k: [kstep][ntile][lane] -> uint4(b0hi,b1hi,b0lo,b1lo)
__device__ uint4 g_Bfrag[NKSTEP * 8 * 32];

// ---------------- helpers ----------------
__device__ __forceinline__ unsigned pack_h2(float x, float y) {
    const __half2 h = __float22half2_rn(make_float2(x, y));
    return *(const unsigned*)&h;
}
__device__ __forceinline__ unsigned pack_hilo(float x, float y, unsigned& lo_out) {
    const __half hx = __float2half_rn(x);
    const __half hy = __float2half_rn(y);
    const __half lx = __float2half_rn(x - __half2float(hx));
    const __half ly = __float2half_rn(y - __half2float(hy));
    lo_out = ((unsigned)__half_as_ushort(ly) << 16) | __half_as_ushort(lx);
    return ((unsigned)__half_as_ushort(hy) << 16) | __half_as_ushort(hx);
}
__device__ __forceinline__ void mma_f16(float* d, const unsigned* a, unsigned b0, unsigned b1) {
    asm volatile(
        "mma.sync.aligned.m16n8k16.row.col.f32.f16.f16.f32 "
        "{%0,%1,%2,%3}, {%4,%5,%6,%7}, {%8,%9}, {%0,%1,%2,%3};"
        : "+f"(d[0]), "+f"(d[1]), "+f"(d[2]), "+f"(d[3])
        : "r"(a[0]), "r"(a[1]), "r"(a[2]), "r"(a[3]), "r"(b0), "r"(b1));
}
__device__ __forceinline__ uint32_t smem_u32(const void* p) {
    uint32_t a;
    asm("{ .reg .u64 t; cvta.to.shared.u64 t, %1; cvt.u32.u64 %0, t; }" : "=r"(a) : "l"(p));
    return a;
}
__device__ __forceinline__ void cp16(uint32_t dst_smem, const void* src_g) {
    asm volatile("cp.async.cg.shared.global [%0], [%1], 16;" :: "r"(dst_smem), "l"(src_g));
}
#define CP_COMMIT() asm volatile("cp.async.commit_group;" ::: "memory")
#define CP_WAIT(n)  asm volatile("cp.async.wait_group %0;" :: "n"(n) : "memory")

// ---------------- Kernel 0: precompute B fragments (permuted-k fp16 hi/lo) ----------
__global__ void __launch_bounds__(256) prep_w_kernel(const float* __restrict__ W) {
    const int idx = blockIdx.x * 256 + threadIdx.x;   // 0 .. 8191
    if (idx >= NKSTEP * 8 * 32) return;
    const int lane = idx & 31;
    const int nt = (idx >> 5) & 7;
    const int s = idx >> 8;
    const int t = lane & 3;
    const int g = lane >> 2;
    const int n = nt * 8 + g;
    const int k0 = s * 16 + t * 4;
    uint4 r;
    unsigned lo;
    r.x = pack_hilo(W[(size_t)k0 * ATTN + n],       W[(size_t)(k0 + 1) * ATTN + n], lo);
    r.z = lo;
    r.y = pack_hilo(W[(size_t)(k0 + 2) * ATTN + n], W[(size_t)(k0 + 3) * ATTN + n], lo);
    r.w = lo;
    g_Bfrag[idx] = r;
}

// ---------------- Kernel 1: hid = hidden @ W_hidden + b_attn (k-parallel) ----------
__global__ void __launch_bounds__(256) hid_kernel(const float* __restrict__ hidden,
                                                  const float* __restrict__ Wh,
                                                  const float* __restrict__ b_attn) {
    __shared__ float sh[HIDDEN];
    __shared__ float part[4][ATTN];
    const int b = blockIdx.x;
    const int tid = threadIdx.x;
    sh[tid] = hidden[b * HIDDEN + tid];
    sh[tid + 256] = hidden[b * HIDDEN + tid + 256];
    __syncthreads();
    const int a = tid & 63;
    const int sl = tid >> 6;      // k-slice 0..3
    float acc = 0.0f;
#pragma unroll 8
    for (int k = sl * 128; k < sl * 128 + 128; k++)
        acc = fmaf(sh[k], Wh[k * ATTN + a], acc);
    part[sl][a] = acc;
    __syncthreads();
    if (tid < 64)
        g_hidb[b * ATTN + tid] = part[0][tid] + part[1][tid] + part[2][tid] + part[3][tid] + b_attn[tid];
}

// ---------------- Kernel 1b: zero partials (keeps score at ncu capture slot #4) ----
__global__ void __launch_bounds__(256) zero_partial_kernel() {
    const int idx = blockIdx.x * 256 + threadIdx.x;
    *(float4*)(g_partial + (size_t)idx * 4) = make_float4(0.f, 0.f, 0.f, 0.f);
}

// ---------------- Kernel 2: fp16 2-product HMMA GEMM, warp-private cp.async pipes --
// 8 warps/CTA, each warp owns 32 rows and its own 4-stage smem pipeline (2KB/stage).
// No __syncthreads in the mainloop — warps are fully decoupled (syncwarp only).
// Stage layout swizzle: 16B chunk c of row r lands at r*16 + ((c+r)&3)*4 floats
// -> conflict-free STS (cp.async) and LDS.128.
__global__ void __launch_bounds__(256, 2) score_kernel(const float* __restrict__ A,
                                                       const float* __restrict__ v) {
    extern __shared__ float sa[];
    const int tid = threadIdx.x;
    const int w = tid >> 5;
    const int lane = tid & 31;
    const int t = lane & 3;
    const int g = lane >> 2;
    const int m0 = blockIdx.x * 256;
    float* ws = sa + w * (STAGES * WSTAGE);
    const uint32_t wsb = smem_u32(ws);

    // cp mapping: instruction i covers local rows i*8 .. i*8+7 (4 lanes x 16B each)
    const int crow = lane >> 2;        // row within 8-row group
    const int cc = lane & 3;           // 16B chunk within 64B slab
    const float* __restrict__ Ab = A + (size_t)(m0 + w * 32) * ENC;

    float d0[8][4], d1[8][4];
#pragma unroll
    for (int nt = 0; nt < 8; nt++)
#pragma unroll
        for (int j = 0; j < 4; j++) { d0[nt][j] = 0.0f; d1[nt][j] = 0.0f; }

    // prologue: stages 0..STAGES-2
#pragma unroll
    for (int st = 0; st < STAGES - 1; st++) {
#pragma unroll
        for (int i = 0; i < 4; i++) {
            const int r = i * 8 + crow;
            cp16(wsb + (uint32_t)(st * WSTAGE + r * 16 + ((cc + r) & 3) * 4) * 4,
                 Ab + (size_t)r * ENC + st * 16 + cc * 4);
        }
        CP_COMMIT();
    }

    const int rot = (t + g) & 3;       // reader swizzle rotation (same for all its rows mod 4)
    const float* sr0 = ws + g * 16 + rot * 4;

#pragma unroll 1
    for (int s = 0; s < NKSTEP; s++) {
        CP_WAIT(STAGES - 2);
        __syncwarp();

        const int sn = s + STAGES - 1;
        if (sn < NKSTEP) {
            const int slot = sn & (STAGES - 1);
#pragma unroll
            for (int i = 0; i < 4; i++) {
                const int r = i * 8 + crow;
                cp16(wsb + (uint32_t)(slot * WSTAGE + r * 16 + ((cc + r) & 3) * 4) * 4,
                     Ab + (size_t)r * ENC + sn * 16 + cc * 4);
            }
        }
        CP_COMMIT();

        const float* sp = sr0 + (s & (STAGES - 1)) * WSTAGE;
        const float4 f0 = *(const float4*)(sp);             // row g
        const float4 f1 = *(const float4*)(sp + 8 * 16);    // row g+8
        const float4 f2 = *(const float4*)(sp + 16 * 16);   // row g+16
        const float4 f3 = *(const float4*)(sp + 24 * 16);   // row g+24
        unsigned a0[4], a1[4];
        a0[0] = pack_h2(f0.x, f0.y);
        a0[1] = pack_h2(f1.x, f1.y);
        a0[2] = pack_h2(f0.z, f0.w);
        a0[3] = pack_h2(f1.z, f1.w);
        a1[0] = pack_h2(f2.x, f2.y);
        a1[1] = pack_h2(f3.x, f3.y);
        a1[2] = pack_h2(f2.z, f2.w);
        a1[3] = pack_h2(f3.z, f3.w);

        const uint4* __restrict__ bp = g_Bfrag + (s << 8) + lane;
#pragma unroll
        for (int nt = 0; nt < 8; nt++) {
            const uint4 bf = bp[nt << 5];
            mma_f16(d0[nt], a0, bf.x, bf.y);   // Ahi * Bhi
            mma_f16(d0[nt], a0, bf.z, bf.w);   // Ahi * Blo
            mma_f16(d1[nt], a1, bf.x, bf.y);
            mma_f16(d1[nt], a1, bf.z, bf.w);
        }
    }

    // Epilogue: scores = sum_n tanh(d + hid[b][n]) * v[n]; 4 rows per lane-group
    const int r0 = m0 + w * 32 + g;
    const int rows[4] = { r0, r0 + 8, r0 + 16, r0 + 24 };
    float p[4] = { 0.f, 0.f, 0.f, 0.f };
#pragma unroll
    for (int nt = 0; nt < 8; nt++) {
        const int n0i = nt * 8 + t * 2;
        const float v0 = v[n0i], v1 = v[n0i + 1];
#pragma unroll
        for (int rr = 0; rr < 4; rr++) {
            const float* hb = g_hidb + (rows[rr] & 63) * ATTN;
            const float e0 = (rr < 2) ? d0[nt][(rr & 1) * 2]     : d1[nt][(rr & 1) * 2];
            const float e1 = (rr < 2) ? d0[nt][(rr & 1) * 2 + 1] : d1[nt][(rr & 1) * 2 + 1];
            p[rr] += tanhf(e0 + hb[n0i]) * v0 + tanhf(e1 + hb[n0i + 1]) * v1;
        }
    }
#pragma unroll
    for (int rr = 0; rr < 4; rr++) {
        p[rr] += __shfl_xor_sync(0xFFFFFFFFu, p[rr], 1);
        p[rr] += __shfl_xor_sync(0xFFFFFFFFu, p[rr], 2);
    }
    if (t == 0) {
#pragma unroll
        for (int rr = 0; rr < 4; rr++)
            g_scoresT[(rows[rr] & 63) * L_SEQ + (rows[rr] >> 6)] = p[rr];
    }
}

// ---------------- Kernel 3a: per-b masked softmax stats (smem-staged) ----------------
__global__ void __launch_bounds__(256) stats_kernel(const int* __restrict__ lens) {
    __shared__ float red[32];
    const int b = blockIdx.x;
    const int tid = threadIdx.x;
    const int lane = tid & 31;
    const int wrp = tid >> 5;
    const int len = lens[b];
    const float* s = g_scoresT + b * L_SEQ;

    float vals[8];
#pragma unroll
    for (int i = 0; i < 2; i++) {
        const float4 f = *(const float4*)(s + (i * 256 + tid) * 4);
        vals[i * 4 + 0] = f.x; vals[i * 4 + 1] = f.y;
        vals[i * 4 + 2] = f.z; vals[i * 4 + 3] = f.w;
    }
    float mx = -INFINITY;
#pragma unroll
    for (int i = 0; i < 2; i++)
#pragma unroll
        for (int j = 0; j < 4; j++) {
            const int l = (i * 256 + tid) * 4 + j;
            if (l < len) mx = fmaxf(mx, vals[i * 4 + j]);
        }
#pragma unroll
    for (int o = 16; o > 0; o >>= 1) mx = fmaxf(mx, __shfl_xor_sync(0xFFFFFFFFu, mx, o));
    if (lane == 0) red[wrp] = mx;
    __syncthreads();
    if (wrp == 0) {
        float m = (lane < 8) ? red[lane] : -INFINITY;
#pragma unroll
        for (int o = 4; o > 0; o >>= 1) m = fmaxf(m, __shfl_xor_sync(0xFFFFFFFFu, m, o));
        if (lane == 0) red[16] = m;
    }
    __syncthreads();
    mx = red[16];

    float sum = 0.0f;
#pragma unroll
    for (int i = 0; i < 2; i++)
#pragma unroll
        for (int j = 0; j < 4; j++) {
            const int l = (i * 256 + tid) * 4 + j;
            if (l < len) sum += expf(vals[i * 4 + j] - mx);
        }
#pragma unroll
    for (int o = 16; o > 0; o >>= 1) sum += __shfl_xor_sync(0xFFFFFFFFu, sum, o);
    if (lane == 0) red[wrp] = sum;
    __syncthreads();
    if (tid == 0) {
        float tot = 0.0f;
#pragma unroll
        for (int i = 0; i < 8; i++) tot += red[i];
        g_stats[b * 2 + 0] = mx;
        g_stats[b * 2 + 1] = 1.0f / tot;
    }
}

// ---------------- Kernel 3b: weighted partial sums (float4, 2-way row split) ----------------
__global__ void __launch_bounds__(256) weighted_kernel(const float* __restrict__ enc,
                                                       const int* __restrict__ lens) {
    __shared__ float wsh[128];
    __shared__ float red[512];
    const int s = blockIdx.x;
    const int b = blockIdx.y;
    const int tid = threadIdx.x;
    const int l0 = s * (L_SEQ / NSPLIT);
    const int len = lens[b];
    float* pbase = g_partial + ((size_t)(s * B_BATCH + b)) * ENC;

    if (l0 >= len) return;   // partials pre-zeroed by zero_partial_kernel

    if (tid < 128) {
        const int l = l0 + tid;
        float w = 0.0f;
        if (l < len)
            w = expf(g_scoresT[b * L_SEQ + l] - g_stats[2 * b]) * g_stats[2 * b + 1];
        wsh[tid] = w;
    }
    __syncthreads();

    const int lim = min(128, len - l0);
    const int d4 = tid & 127;
    const int half = tid >> 7;
    float4 acc = make_float4(0.f, 0.f, 0.f, 0.f);
#pragma unroll 4
    for (int i = half; i < lim; i += 2) {
        const float w = wsh[i];
        const float4 e = *(const float4*)(enc + ((size_t)(l0 + i) * B_BATCH + b) * ENC + d4 * 4);
        acc.x = fmaf(w, e.x, acc.x);
        acc.y = fmaf(w, e.y, acc.y);
        acc.z = fmaf(w, e.z, acc.z);
        acc.w = fmaf(w, e.w, acc.w);
    }
    if (half == 1) *(float4*)&red[d4 * 4] = acc;
    __syncthreads();
    if (half == 0) {
        const float4 o = *(const float4*)&red[d4 * 4];
        acc.x += o.x; acc.y += o.y; acc.z += o.z; acc.w += o.w;
        *(float4*)(pbase + d4 * 4) = acc;
    }
}

// ---------------- Kernel 3c: reduce partials ----------------
__global__ void __launch_bounds__(256) reduce_kernel(float* __restrict__ out) {
    const int idx = blockIdx.x * 256 + threadIdx.x;
    float4 sum = make_float4(0.f, 0.f, 0.f, 0.f);
#pragma unroll
    for (int s = 0; s < NSPLIT; s++) {
        const float4 p = *(const float4*)(g_partial + (size_t)s * (B_BATCH * ENC) + idx * 4);
        sum.x += p.x; sum.y += p.y; sum.z += p.z; sum.w += p.w;
    }
    *(float4*)(out + idx * 4) = sum;
}

// ---------------- Launch ----------------
extern "C" void kernel_launch(void* const* d_in, const int* in_sizes, int n_in,
                              void* d_out, int out_size) {
    const float* enc    = (const float*)d_in[0];  // (L, B, 512)
    const int*   lens   = (const int*)d_in[1];    // (B,)
    const float* hidden = (const float*)d_in[2];  // (B, 512)
    const float* W_enc  = (const float*)d_in[3];  // (512, 64)
    const float* b_attn = (const float*)d_in[4];  // (64,)
    const float* W_hid  = (const float*)d_in[5];  // (512, 64)
    const float* v      = (const float*)d_in[6];  // (64,)
    float* out = (float*)d_out;                   // (B, 512)

    cudaFuncSetAttribute(score_kernel, cudaFuncAttributeMaxDynamicSharedMemorySize, SMEM_BYTES);

    prep_w_kernel<<<32, 256>>>(W_enc);                            // 1
    hid_kernel<<<B_BATCH, 256>>>(hidden, W_hid, b_attn);          // 2
    zero_partial_kernel<<<NSPLIT * B_BATCH * ENC / 1024, 256>>>();// 3
    score_kernel<<<M_TOTAL / 256, 256, SMEM_BYTES>>>(enc, v);     // 4  <- ncu capture slot
    stats_kernel<<<B_BATCH, 256>>>(lens);                         // 5
    weighted_kernel<<<dim3(NSPLIT, B_BATCH), 256>>>(enc, lens);   // 6
    reduce_kernel<<<(B_BATCH * ENC) / (256 * 4), 256>>>(out);     // 7
}

// round 9
// speedup vs baseline: 1.3810x; 1.0003x over previous
#include <cuda_runtime.h>
#include <cuda_bf16.h>
#include <cuda_fp16.h>
#include <cstdint>
#include <math.h>

// Problem constants
#define L_SEQ 2048
#define B_BATCH 64
#define ENC 512
#define ATTN 64
#define HIDDEN 512
#define M_TOTAL (L_SEQ * B_BATCH)   // 131072
#define NSPLIT 16
#define NKSTEP 32                   // 512 / 16
#define STAGES 3                    // per-warp cp.async pipeline depth (3 -> 48KB/CTA,
                                    // leaves ~132KB L1 so the 128KB B table is resident)
#define WSTAGE 512                  // floats per warp-stage (32 rows x 16)
#define SMEM_BYTES (8 * STAGES * WSTAGE * 4)   // 48 KB

// ---------------- device-global scratch (no allocs allowed) ----------------
__device__ float g_hidb[B_BATCH * ATTN];               // hid @ W_hidden + b_attn, (b, a)
__device__ float g_scoresT[B_BATCH * L_SEQ];           // scores transposed (b, l)
__device__ float g_stats[B_BATCH * 2];                 // per-b: max, 1/sumexp
__device__ float g_partial[NSPLIT * B_BATCH * ENC];    // partial weighted sums
// B fragments, mma-native with PERMUTED k: [kstep][ntile][lane] -> uint4(b0hi,b1hi,b0lo,b1lo)
__device__ uint4 g_Bfrag[NKSTEP * 8 * 32];

// ---------------- helpers ----------------
__device__ __forceinline__ unsigned pack_h2(float x, float y) {
    const __half2 h = __float22half2_rn(make_float2(x, y));
    return *(const unsigned*)&h;
}
__device__ __forceinline__ unsigned pack_hilo(float x, float y, unsigned& lo_out) {
    const __half hx = __float2half_rn(x);
    const __half hy = __float2half_rn(y);
    const __half lx = __float2half_rn(x - __half2float(hx));
    const __half ly = __float2half_rn(y - __half2float(hy));
    lo_out = ((unsigned)__half_as_ushort(ly) << 16) | __half_as_ushort(lx);
    return ((unsigned)__half_as_ushort(hy) << 16) | __half_as_ushort(hx);
}
__device__ __forceinline__ void mma_f16(float* d, const unsigned* a, unsigned b0, unsigned b1) {
    asm volatile(
        "mma.sync.aligned.m16n8k16.row.col.f32.f16.f16.f32 "
        "{%0,%1,%2,%3}, {%4,%5,%6,%7}, {%8,%9}, {%0,%1,%2,%3};"
        : "+f"(d[0]), "+f"(d[1]), "+f"(d[2]), "+f"(d[3])
        : "r"(a[0]), "r"(a[1]), "r"(a[2]), "r"(a[3]), "r"(b0), "r"(b1));
}
__device__ __forceinline__ uint32_t smem_u32(const void* p) {
    uint32_t a;
    asm("{ .reg .u64 t; cvta.to.shared.u64 t, %1; cvt.u32.u64 %0, t; }" : "=r"(a) : "l"(p));
    return a;
}
__device__ __forceinline__ void cp16(uint32_t dst_smem, const void* src_g) {
    asm volatile("cp.async.cg.shared.global [%0], [%1], 16;" :: "r"(dst_smem), "l"(src_g));
}
#define CP_COMMIT() asm volatile("cp.async.commit_group;" ::: "memory")
#define CP_WAIT(n)  asm volatile("cp.async.wait_group %0;" :: "n"(n) : "memory")

// ---------------- Kernel 0: precompute B fragments (permuted-k fp16 hi/lo) ----------
__global__ void __launch_bounds__(256) prep_w_kernel(const float* __restrict__ W) {
    const int idx = blockIdx.x * 256 + threadIdx.x;   // 0 .. 8191
    if (idx >= NKSTEP * 8 * 32) return;
    const int lane = idx & 31;
    const int nt = (idx >> 5) & 7;
    const int s = idx >> 8;
    const int t = lane & 3;
    const int g = lane >> 2;
    const int n = nt * 8 + g;
    const int k0 = s * 16 + t * 4;
    uint4 r;
    unsigned lo;
    r.x = pack_hilo(W[(size_t)k0 * ATTN + n],       W[(size_t)(k0 + 1) * ATTN + n], lo);
    r.z = lo;
    r.y = pack_hilo(W[(size_t)(k0 + 2) * ATTN + n], W[(size_t)(k0 + 3) * ATTN + n], lo);
    r.w = lo;
    g_Bfrag[idx] = r;
}

// ---------------- Kernel 1: hid = hidden @ W_hidden + b_attn (k-parallel) ----------
__global__ void __launch_bounds__(256) hid_kernel(const float* __restrict__ hidden,
                                                  const float* __restrict__ Wh,
                                                  const float* __restrict__ b_attn) {
    __shared__ float sh[HIDDEN];
    __shared__ float part[4][ATTN];
    const int b = blockIdx.x;
    const int tid = threadIdx.x;
    sh[tid] = hidden[b * HIDDEN + tid];
    sh[tid + 256] = hidden[b * HIDDEN + tid + 256];
    __syncthreads();
    const int a = tid & 63;
    const int sl = tid >> 6;      // k-slice 0..3
    float acc = 0.0f;
#pragma unroll 8
    for (int k = sl * 128; k < sl * 128 + 128; k++)
        acc = fmaf(sh[k], Wh[k * ATTN + a], acc);
    part[sl][a] = acc;
    __syncthreads();
    if (tid < 64)
        g_hidb[b * ATTN + tid] = part[0][tid] + part[1][tid] + part[2][tid] + part[3][tid] + b_attn[tid];
}

// ---------------- Kernel 1b: zero partials (keeps score at ncu capture slot #4) ----
__global__ void __launch_bounds__(256) zero_partial_kernel() {
    const int idx = blockIdx.x * 256 + threadIdx.x;
    *(float4*)(g_partial + (size_t)idx * 4) = make_float4(0.f, 0.f, 0.f, 0.f);
}

// ---------------- Kernel 2: fp16 2-product HMMA GEMM, warp-private cp.async pipes --
// 8 warps/CTA, each warp owns 32 rows and its own 3-stage smem pipeline (2KB/stage).
// No __syncthreads in the mainloop. cp.async.cg bypasses L1, so the 128KB B-fragment
// table stays L1-resident (L1 = 228 - 2*48 = 132KB).
__global__ void __launch_bounds__(256, 2) score_kernel(const float* __restrict__ A,
                                                       const float* __restrict__ v) {
    extern __shared__ float sa[];
    const int tid = threadIdx.x;
    const int w = tid >> 5;
    const int lane = tid & 31;
    const int t = lane & 3;
    const int g = lane >> 2;
    const int m0 = blockIdx.x * 256;
    float* ws = sa + w * (STAGES * WSTAGE);
    const uint32_t wsb = smem_u32(ws);

    // cp mapping: instruction i covers local rows i*8 .. i*8+7 (4 lanes x 16B each)
    const int crow = lane >> 2;        // row within 8-row group
    const int cc = lane & 3;           // 16B chunk within 64B slab
    const float* __restrict__ Ab = A + (size_t)(m0 + w * 32) * ENC;

    float d0[8][4], d1[8][4];
#pragma unroll
    for (int nt = 0; nt < 8; nt++)
#pragma unroll
        for (int j = 0; j < 4; j++) { d0[nt][j] = 0.0f; d1[nt][j] = 0.0f; }

    // prologue: stages 0..STAGES-2
#pragma unroll
    for (int st = 0; st < STAGES - 1; st++) {
#pragma unroll
        for (int i = 0; i < 4; i++) {
            const int r = i * 8 + crow;
            cp16(wsb + (uint32_t)(st * WSTAGE + r * 16 + ((cc + r) & 3) * 4) * 4,
                 Ab + (size_t)r * ENC + st * 16 + cc * 4);
        }
        CP_COMMIT();
    }

    const int rot = (t + g) & 3;       // reader swizzle rotation
    const float* sr0 = ws + g * 16 + rot * 4;

    int cs = 0;                        // compute slot
    int ps = STAGES - 1;               // prefetch slot

#pragma unroll 1
    for (int s = 0; s < NKSTEP; s++) {
        CP_WAIT(STAGES - 2);
        __syncwarp();

        const int sn = s + STAGES - 1;
        if (sn < NKSTEP) {
#pragma unroll
            for (int i = 0; i < 4; i++) {
                const int r = i * 8 + crow;
                cp16(wsb + (uint32_t)(ps * WSTAGE + r * 16 + ((cc + r) & 3) * 4) * 4,
                     Ab + (size_t)r * ENC + sn * 16 + cc * 4);
            }
        }
        CP_COMMIT();

        const float* sp = sr0 + cs * WSTAGE;
        const float4 f0 = *(const float4*)(sp);             // row g
        const float4 f1 = *(const float4*)(sp + 8 * 16);    // row g+8
        const float4 f2 = *(const float4*)(sp + 16 * 16);   // row g+16
        const float4 f3 = *(const float4*)(sp + 24 * 16);   // row g+24
        unsigned a0[4], a1[4];
        a0[0] = pack_h2(f0.x, f0.y);
        a0[1] = pack_h2(f1.x, f1.y);
        a0[2] = pack_h2(f0.z, f0.w);
        a0[3] = pack_h2(f1.z, f1.w);
        a1[0] = pack_h2(f2.x, f2.y);
        a1[1] = pack_h2(f3.x, f3.y);
        a1[2] = pack_h2(f2.z, f2.w);
        a1[3] = pack_h2(f3.z, f3.w);

        const uint4* __restrict__ bp = g_Bfrag + (s << 8) + lane;
#pragma unroll
        for (int nt = 0; nt < 8; nt++) {
            const uint4 bf = bp[nt << 5];
            mma_f16(d0[nt], a0, bf.x, bf.y);   // Ahi * Bhi
            mma_f16(d0[nt], a0, bf.z, bf.w);   // Ahi * Blo
            mma_f16(d1[nt], a1, bf.x, bf.y);
            mma_f16(d1[nt], a1, bf.z, bf.w);
        }

        cs = (cs == STAGES - 1) ? 0 : cs + 1;
        ps = (ps == STAGES - 1) ? 0 : ps + 1;
    }

    // Epilogue: scores = sum_n tanh(d + hid[b][n]) * v[n]; 4 rows per lane-group
    const int r0 = m0 + w * 32 + g;
    const int rows[4] = { r0, r0 + 8, r0 + 16, r0 + 24 };
    float p[4] = { 0.f, 0.f, 0.f, 0.f };
#pragma unroll
    for (int nt = 0; nt < 8; nt++) {
        const int n0i = nt * 8 + t * 2;
        const float v0 = v[n0i], v1 = v[n0i + 1];
#pragma unroll
        for (int rr = 0; rr < 4; rr++) {
            const float* hb = g_hidb + (rows[rr] & 63) * ATTN;
            const float e0 = (rr < 2) ? d0[nt][(rr & 1) * 2]     : d1[nt][(rr & 1) * 2];
            const float e1 = (rr < 2) ? d0[nt][(rr & 1) * 2 + 1] : d1[nt][(rr & 1) * 2 + 1];
            p[rr] += tanhf(e0 + hb[n0i]) * v0 + tanhf(e1 + hb[n0i + 1]) * v1;
        }
    }
#pragma unroll
    for (int rr = 0; rr < 4; rr++) {
        p[rr] += __shfl_xor_sync(0xFFFFFFFFu, p[rr], 1);
        p[rr] += __shfl_xor_sync(0xFFFFFFFFu, p[rr], 2);
    }
    if (t == 0) {
#pragma unroll
        for (int rr = 0; rr < 4; rr++)
            g_scoresT[(rows[rr] & 63) * L_SEQ + (rows[rr] >> 6)] = p[rr];
    }
}

// ---------------- Kernel 3a: per-b masked softmax stats (smem-staged) ----------------
__global__ void __launch_bounds__(256) stats_kernel(const int* __restrict__ lens) {
    __shared__ float red[32];
    const int b = blockIdx.x;
    const int tid = threadIdx.x;
    const int lane = tid & 31;
    const int wrp = tid >> 5;
    const int len = lens[b];
    const float* s = g_scoresT + b * L_SEQ;

    float vals[8];
#pragma unroll
    for (int i = 0; i < 2; i++) {
        const float4 f = *(const float4*)(s + (i * 256 + tid) * 4);
        vals[i * 4 + 0] = f.x; vals[i * 4 + 1] = f.y;
        vals[i * 4 + 2] = f.z; vals[i * 4 + 3] = f.w;
    }
    float mx = -INFINITY;
#pragma unroll
    for (int i = 0; i < 2; i++)
#pragma unroll
        for (int j = 0; j < 4; j++) {
            const int l = (i * 256 + tid) * 4 + j;
            if (l < len) mx = fmaxf(mx, vals[i * 4 + j]);
        }
#pragma unroll
    for (int o = 16; o > 0; o >>= 1) mx = fmaxf(mx, __shfl_xor_sync(0xFFFFFFFFu, mx, o));
    if (lane == 0) red[wrp] = mx;
    __syncthreads();
    if (wrp == 0) {
        float m = (lane < 8) ? red[lane] : -INFINITY;
#pragma unroll
        for (int o = 4; o > 0; o >>= 1) m = fmaxf(m, __shfl_xor_sync(0xFFFFFFFFu, m, o));
        if (lane == 0) red[16] = m;
    }
    __syncthreads();
    mx = red[16];

    float sum = 0.0f;
#pragma unroll
    for (int i = 0; i < 2; i++)
#pragma unroll
        for (int j = 0; j < 4; j++) {
            const int l = (i * 256 + tid) * 4 + j;
            if (l < len) sum += expf(vals[i * 4 + j] - mx);
        }
#pragma unroll
    for (int o = 16; o > 0; o >>= 1) sum += __shfl_xor_sync(0xFFFFFFFFu, sum, o);
    if (lane == 0) red[wrp] = sum;
    __syncthreads();
    if (tid == 0) {
        float tot = 0.0f;
#pragma unroll
        for (int i = 0; i < 8; i++) tot += red[i];
        g_stats[b * 2 + 0] = mx;
        g_stats[b * 2 + 1] = 1.0f / tot;
    }
}

// ---------------- Kernel 3b: weighted partial sums (float4, 2-way row split) ----------------
__global__ void __launch_bounds__(256) weighted_kernel(const float* __restrict__ enc,
                                                       const int* __restrict__ lens) {
    __shared__ float wsh[128];
    __shared__ float red[512];
    const int s = blockIdx.x;
    const int b = blockIdx.y;
    const int tid = threadIdx.x;
    const int l0 = s * (L_SEQ / NSPLIT);
    const int len = lens[b];
    float* pbase = g_partial + ((size_t)(s * B_BATCH + b)) * ENC;

    if (l0 >= len) return;   // partials pre-zeroed by zero_partial_kernel

    if (tid < 128) {
        const int l = l0 + tid;
        float w = 0.0f;
        if (l < len)
            w = expf(g_scoresT[b * L_SEQ + l] - g_stats[2 * b]) * g_stats[2 * b + 1];
        wsh[tid] = w;
    }
    __syncthreads();

    const int lim = min(128, len - l0);
    const int d4 = tid & 127;
    const int half = tid >> 7;
    float4 acc = make_float4(0.f, 0.f, 0.f, 0.f);
#pragma unroll 8
    for (int i = half; i < lim; i += 2) {
        const float w = wsh[i];
        const float4 e = *(const float4*)(enc + ((size_t)(l0 + i) * B_BATCH + b) * ENC + d4 * 4);
        acc.x = fmaf(w, e.x, acc.x);
        acc.y = fmaf(w, e.y, acc.y);
        acc.z = fmaf(w, e.z, acc.z);
        acc.w = fmaf(w, e.w, acc.w);
    }
    if (half == 1) *(float4*)&red[d4 * 4] = acc;
    __syncthreads();
    if (half == 0) {
        const float4 o = *(const float4*)&red[d4 * 4];
        acc.x += o.x; acc.y += o.y; acc.z += o.z; acc.w += o.w;
        *(float4*)(pbase + d4 * 4) = acc;
    }
}

// ---------------- Kernel 3c: reduce partials ----------------
__global__ void __launch_bounds__(256) reduce_kernel(float* __restrict__ out) {
    const int idx = blockIdx.x * 256 + threadIdx.x;
    float4 sum = make_float4(0.f, 0.f, 0.f, 0.f);
#pragma unroll
    for (int s = 0; s < NSPLIT; s++) {
        const float4 p = *(const float4*)(g_partial + (size_t)s * (B_BATCH * ENC) + idx * 4);
        sum.x += p.x; sum.y += p.y; sum.z += p.z; sum.w += p.w;
    }
    *(float4*)(out + idx * 4) = sum;
}

// ---------------- Launch ----------------
extern "C" void kernel_launch(void* const* d_in, const int* in_sizes, int n_in,
                              void* d_out, int out_size) {
    const float* enc    = (const float*)d_in[0];  // (L, B, 512)
    const int*   lens   = (const int*)d_in[1];    // (B,)
    const float* hidden = (const float*)d_in[2];  // (B, 512)
    const float* W_enc  = (const float*)d_in[3];  // (512, 64)
    const float* b_attn = (const float*)d_in[4];  // (64,)
    const float* W_hid  = (const float*)d_in[5];  // (512, 64)
    const float* v      = (const float*)d_in[6];  // (64,)
    float* out = (float*)d_out;                   // (B, 512)

    cudaFuncSetAttribute(score_kernel, cudaFuncAttributeMaxDynamicSharedMemorySize, SMEM_BYTES);

    prep_w_kernel<<<32, 256>>>(W_enc);                            // 1
    hid_kernel<<<B_BATCH, 256>>>(hidden, W_hid, b_attn);          // 2
    zero_partial_kernel<<<NSPLIT * B_BATCH * ENC / 1024, 256>>>();// 3
    score_kernel<<<M_TOTAL / 256, 256, SMEM_BYTES>>>(enc, v);     // 4  <- ncu capture slot
    stats_kernel<<<B_BATCH, 256>>>(lens);                         // 5
    weighted_kernel<<<dim3(NSPLIT, B_BATCH), 256>>>(enc, lens);   // 6
    reduce_kernel<<<(B_BATCH * ENC) / (256 * 4), 256>>>(out);     // 7
}